// round 8
// baseline (speedup 1.0000x reference)
#include <cuda_runtime.h>
#include <cuda_bf16.h>
#include <cstdint>

#define N_NODES    50000
#define N_EDGES    800000
#define HIDDEN     128
#define NUM_GRAPHS 512

// ================= scratch (static device globals; no allocation) =================
__device__ __nv_bfloat16 g_Ahi[N_NODES * HIDDEN];
__device__ __nv_bfloat16 g_Alo[N_NODES * HIDDEN];
__device__ float         g_H[N_NODES * HIDDEN];
__device__ __nv_bfloat16 g_Whi[4][HIDDEN * HIDDEN];   // transposed: [n][k]
__device__ __nv_bfloat16 g_Wlo[4][HIDDEN * HIDDEN];
__device__ int    g_deg[N_NODES];
__device__ int    g_rowptr[N_NODES + 1];
__device__ int    g_cursor[N_NODES];
__device__ int    g_col[N_EDGES];
__device__ float  g_pool[NUM_GRAPHS * HIDDEN];

// ================= prep: zero scratch + convert all 4 weights =================
__global__ void prep_kernel(const float* __restrict__ W0, const float* __restrict__ W1,
                            const float* __restrict__ W2, const float* __restrict__ W3) {
    int i = blockIdx.x * blockDim.x + threadIdx.x;
    int st = gridDim.x * blockDim.x;
    for (int j = i; j < N_NODES; j += st) g_deg[j] = 0;
    for (int j = i; j < NUM_GRAPHS * HIDDEN; j += st) g_pool[j] = 0.0f;
    const float* Wt[4] = {W0, W1, W2, W3};
    #pragma unroll
    for (int q = 0; q < 4; q++) {
        const float* W = Wt[q];
        for (int j = i; j < HIDDEN * HIDDEN; j += st) {
            int k = j >> 7, n = j & 127;           // W[k][n] row-major
            float v = W[j];
            __nv_bfloat16 h = __float2bfloat16(v);
            g_Whi[q][n * 128 + k] = h;             // B[n][k] = W[k][n]
            g_Wlo[q][n * 128 + k] = __float2bfloat16(v - __bfloat162float(h));
        }
    }
}

// ================= degree histogram (4 edges / thread) =================
__global__ void hist_kernel(const int* __restrict__ ei) {
    int t = blockIdx.x * blockDim.x + threadIdx.x;
    if (t >= N_EDGES / 4) return;
    int4 d = ((const int4*)(ei + N_EDGES))[t];
    if ((unsigned)d.x < (unsigned)N_NODES) atomicAdd(&g_deg[d.x], 1);
    if ((unsigned)d.y < (unsigned)N_NODES) atomicAdd(&g_deg[d.y], 1);
    if ((unsigned)d.z < (unsigned)N_NODES) atomicAdd(&g_deg[d.z], 1);
    if ((unsigned)d.w < (unsigned)N_NODES) atomicAdd(&g_deg[d.w], 1);
}

// ================= exclusive scan (single block, int4 per thread) =================
__global__ void scan_kernel() {
    __shared__ int warp_sums[32];
    __shared__ int s_carry;
    int tid = threadIdx.x, lane = tid & 31, w = tid >> 5;
    if (tid == 0) { s_carry = 0; g_rowptr[0] = 0; }
    __syncthreads();
    const int N4 = N_NODES / 4;   // 12500
    for (int base = 0; base < N4; base += 1024) {
        int i4 = base + tid;
        int4 v = make_int4(0, 0, 0, 0);
        if (i4 < N4) v = ((const int4*)g_deg)[i4];
        int s0 = v.x, s1 = s0 + v.y, s2 = s1 + v.z, s3 = s2 + v.w;
        int tot = s3;
        int inc = tot;
        #pragma unroll
        for (int o = 1; o < 32; o <<= 1) {
            int t = __shfl_up_sync(0xFFFFFFFFu, inc, o);
            if (lane >= o) inc += t;
        }
        if (lane == 31) warp_sums[w] = inc;
        __syncthreads();
        if (w == 0) {
            int s = warp_sums[lane];
            int si = s;
            #pragma unroll
            for (int o = 1; o < 32; o <<= 1) {
                int t = __shfl_up_sync(0xFFFFFFFFu, si, o);
                if (lane >= o) si += t;
            }
            warp_sums[lane] = si - s;
        }
        __syncthreads();
        int off = s_carry + warp_sums[w] + (inc - tot);
        if (i4 < N4) {
            int b = i4 * 4;
            ((int4*)g_cursor)[i4] = make_int4(off, off + s0, off + s1, off + s2);
            g_rowptr[b + 1] = off + s0;
            g_rowptr[b + 2] = off + s1;
            g_rowptr[b + 3] = off + s2;
            g_rowptr[b + 4] = off + s3;
        }
        __syncthreads();
        int lastT = min(1024, N4 - base) - 1;
        if (tid == lastT) s_carry = off + tot;
        __syncthreads();
    }
}

// ================= CSR fill (4 edges / thread) =================
__global__ void fill_kernel(const int* __restrict__ ei) {
    int t = blockIdx.x * blockDim.x + threadIdx.x;
    if (t >= N_EDGES / 4) return;
    int4 s = ((const int4*)ei)[t];
    int4 d = ((const int4*)(ei + N_EDGES))[t];
    if ((unsigned)d.x < (unsigned)N_NODES && (unsigned)s.x < (unsigned)N_NODES)
        g_col[atomicAdd(&g_cursor[d.x], 1)] = s.x;
    if ((unsigned)d.y < (unsigned)N_NODES && (unsigned)s.y < (unsigned)N_NODES)
        g_col[atomicAdd(&g_cursor[d.y], 1)] = s.y;
    if ((unsigned)d.z < (unsigned)N_NODES && (unsigned)s.z < (unsigned)N_NODES)
        g_col[atomicAdd(&g_cursor[d.z], 1)] = s.z;
    if ((unsigned)d.w < (unsigned)N_NODES && (unsigned)s.w < (unsigned)N_NODES)
        g_col[atomicAdd(&g_cursor[d.w], 1)] = s.w;
}

// ================= aggregation + split-bf16 conversion =================
__global__ void agg_conv_kernel(const float4* __restrict__ in,
                                __nv_bfloat16* __restrict__ Ohi,
                                __nv_bfloat16* __restrict__ Olo) {
    int gw = (blockIdx.x * blockDim.x + threadIdx.x) >> 5;
    if (gw >= N_NODES) return;
    int lane = threadIdx.x & 31;
    float4 acc = in[gw * 32 + lane];
    int s = g_rowptr[gw], e = g_rowptr[gw + 1];
    int j = (s < e) ? g_col[s] : 0;
    for (int p = s; p < e; p++) {
        int jn = (p + 1 < e) ? g_col[p + 1] : 0;
        float4 v = in[j * 32 + lane];
        acc.x += v.x; acc.y += v.y; acc.z += v.z; acc.w += v.w;
        j = jn;
    }
    __nv_bfloat16 hx = __float2bfloat16(acc.x), hy = __float2bfloat16(acc.y);
    __nv_bfloat16 hz = __float2bfloat16(acc.z), hw = __float2bfloat16(acc.w);
    __nv_bfloat162 hp0; hp0.x = hx; hp0.y = hy;
    __nv_bfloat162 hp1; hp1.x = hz; hp1.y = hw;
    __nv_bfloat162 lp0; lp0.x = __float2bfloat16(acc.x - __bfloat162float(hx));
                        lp0.y = __float2bfloat16(acc.y - __bfloat162float(hy));
    __nv_bfloat162 lp1; lp1.x = __float2bfloat16(acc.z - __bfloat162float(hz));
                        lp1.y = __float2bfloat16(acc.w - __bfloat162float(hw));
    uint2 hv; hv.x = *(uint32_t*)&hp0; hv.y = *(uint32_t*)&hp1;
    uint2 lv; lv.x = *(uint32_t*)&lp0; lv.y = *(uint32_t*)&lp1;
    *(uint2*)(Ohi + (size_t)gw * 128 + lane * 4) = hv;
    *(uint2*)(Olo + (size_t)gw * 128 + lane * 4) = lv;
}

// ================= fused MLP: relu((relu(A@W1+b1))@W2+b2), HMMA split-bf16 =================
// MODE 1: write fp32   MODE 2: fused mean-pool atomics
#define SA 136                        // padded smem row stride (elements)
static constexpr int R_AHI  = 0;
static constexpr int R_ALO  = 34816;
static constexpr int R_W1H  = 69632;
static constexpr int R_W1L  = 104448;
static constexpr int R_W2H  = 139264;
static constexpr int R_W2L  = 174080;
static constexpr int OFF_B1 = 208896;
static constexpr int OFF_B2 = 209408;
static constexpr int OFF_BT = 209920;
static constexpr int MLP_SMEM = 210432;

__device__ __forceinline__ void mma16816(float* c,
    uint32_t a0, uint32_t a1, uint32_t a2, uint32_t a3, uint32_t b0, uint32_t b1) {
    asm volatile(
        "mma.sync.aligned.m16n8k16.row.col.f32.bf16.bf16.f32 "
        "{%0,%1,%2,%3}, {%4,%5,%6,%7}, {%8,%9}, {%0,%1,%2,%3};"
        : "+f"(c[0]), "+f"(c[1]), "+f"(c[2]), "+f"(c[3])
        : "r"(a0), "r"(a1), "r"(a2), "r"(a3), "r"(b0), "r"(b1));
}

// one full 128x128x128 split-GEMM pass: acc += A(smem) @ W(smem), 3-term hi/lo
__device__ __forceinline__ void gemm_pass(
    const __nv_bfloat16* sAhi, const __nv_bfloat16* sAlo,
    const __nv_bfloat16* sWhi, const __nv_bfloat16* sWlo,
    int aBase, int bBase, float acc[2][4][4])
{
    #pragma unroll
    for (int kk = 0; kk < 8; kk++) {
        int k0 = kk * 16;
        uint32_t ah[2][4], al[2][4];
        #pragma unroll
        for (int ma = 0; ma < 2; ma++) {
            int b = aBase + ma * 16 * SA + k0;
            ah[ma][0] = *(const uint32_t*)(sAhi + b);
            ah[ma][1] = *(const uint32_t*)(sAhi + b + 8 * SA);
            ah[ma][2] = *(const uint32_t*)(sAhi + b + 8);
            ah[ma][3] = *(const uint32_t*)(sAhi + b + 8 * SA + 8);
            al[ma][0] = *(const uint32_t*)(sAlo + b);
            al[ma][1] = *(const uint32_t*)(sAlo + b + 8 * SA);
            al[ma][2] = *(const uint32_t*)(sAlo + b + 8);
            al[ma][3] = *(const uint32_t*)(sAlo + b + 8 * SA + 8);
        }
        uint32_t bh[4][2], bl[4][2];
        #pragma unroll
        for (int nb = 0; nb < 4; nb++) {
            int b = bBase + nb * 8 * SA + k0;
            bh[nb][0] = *(const uint32_t*)(sWhi + b);
            bh[nb][1] = *(const uint32_t*)(sWhi + b + 8);
            bl[nb][0] = *(const uint32_t*)(sWlo + b);
            bl[nb][1] = *(const uint32_t*)(sWlo + b + 8);
        }
        #pragma unroll
        for (int ma = 0; ma < 2; ma++)
            #pragma unroll
            for (int nb = 0; nb < 4; nb++) {
                mma16816(acc[ma][nb], ah[ma][0], ah[ma][1], ah[ma][2], ah[ma][3], bh[nb][0], bh[nb][1]);
                mma16816(acc[ma][nb], ah[ma][0], ah[ma][1], ah[ma][2], ah[ma][3], bl[nb][0], bl[nb][1]);
                mma16816(acc[ma][nb], al[ma][0], al[ma][1], al[ma][2], al[ma][3], bh[nb][0], bh[nb][1]);
            }
    }
}

template <int MODE>
__global__ void __launch_bounds__(512) mlp_mma(
    const __nv_bfloat16* __restrict__ Ahi, const __nv_bfloat16* __restrict__ Alo,
    const __nv_bfloat16* __restrict__ W1hi, const __nv_bfloat16* __restrict__ W1lo,
    const float* __restrict__ b1,
    const __nv_bfloat16* __restrict__ W2hi, const __nv_bfloat16* __restrict__ W2lo,
    const float* __restrict__ b2,
    float* __restrict__ Of32, const int* __restrict__ batch)
{
    extern __shared__ char sh[];
    __nv_bfloat16* sAhi = (__nv_bfloat16*)(sh + R_AHI);
    __nv_bfloat16* sAlo = (__nv_bfloat16*)(sh + R_ALO);
    float* sb1 = (float*)(sh + OFF_B1);
    float* sb2 = (float*)(sh + OFF_B2);
    int*   sbatch = (int*)(sh + OFF_BT);

    int tid = threadIdx.x;
    int row0 = blockIdx.x * 128;
    int nr = min(128, N_NODES - row0);

    if (tid < 128) {
        sb1[tid] = b1[tid];
        sb2[tid] = b2[tid];
        if (MODE == 2) sbatch[tid] = (tid < nr) ? batch[row0 + tid] : -1;
    }

    // ---- stage 6 tiles: A(hi,lo) guarded, W1(hi,lo), W2(hi,lo) ----
    const uint4 z = make_uint4(0, 0, 0, 0);
    const __nv_bfloat16* gsrc[6] = {Ahi, Alo, W1hi, W1lo, W2hi, W2lo};
    const int goff[6] = {R_AHI, R_ALO, R_W1H, R_W1L, R_W2H, R_W2L};
    #pragma unroll
    for (int t6 = 0; t6 < 6; t6++) {
        const __nv_bfloat16* src = gsrc[t6];
        __nv_bfloat16* dstb = (__nv_bfloat16*)(sh + goff[t6]);
        bool isA = (t6 < 2);
        #pragma unroll
        for (int it = 0; it < 4; it++) {
            int idx = tid + it * 512;          // 0..2047
            int r = idx >> 4, c = idx & 15;    // 16 uint4 per 128-elem row
            uint4 v;
            if (isA) v = (r < nr) ? *(const uint4*)(src + (size_t)(row0 + r) * 128 + c * 8) : z;
            else     v = *(const uint4*)(src + (size_t)r * 128 + c * 8);
            *(uint4*)(dstb + r * SA + c * 8) = v;
        }
    }
    __syncthreads();

    int wid = tid >> 5, lid = tid & 31;
    int warp_m = wid >> 2, warp_n = wid & 3;   // 4x4 warp grid, warp tile 32x32
    int gid = lid >> 2, tig = lid & 3;
    int aBase = (warp_m * 32 + gid) * SA + tig * 2;
    int bBase = (warp_n * 32 + gid) * SA + tig * 2;

    float acc[2][4][4];
    #pragma unroll
    for (int ma = 0; ma < 2; ma++)
        #pragma unroll
        for (int nb = 0; nb < 4; nb++)
            #pragma unroll
            for (int q = 0; q < 4; q++) acc[ma][nb][q] = 0.0f;

    // ---- GEMM1: A @ W1 ----
    gemm_pass(sAhi, sAlo, (__nv_bfloat16*)(sh + R_W1H), (__nv_bfloat16*)(sh + R_W1L),
              aBase, bBase, acc);
    __syncthreads();   // all reads of A-tiles done; safe to overwrite

    // ---- intermediate: bias1 + relu + hi/lo split back into A-tile smem ----
    #pragma unroll
    for (int ma = 0; ma < 2; ma++)
        #pragma unroll
        for (int nb = 0; nb < 4; nb++) {
            int col = warp_n * 32 + nb * 8 + tig * 2;
            float bs0 = sb1[col], bs1 = sb1[col + 1];
            int r1 = warp_m * 32 + ma * 16 + gid;
            int r2 = r1 + 8;
            float v0 = fmaxf(acc[ma][nb][0] + bs0, 0.0f);
            float v1 = fmaxf(acc[ma][nb][1] + bs1, 0.0f);
            float v2 = fmaxf(acc[ma][nb][2] + bs0, 0.0f);
            float v3 = fmaxf(acc[ma][nb][3] + bs1, 0.0f);
            __nv_bfloat16 h0 = __float2bfloat16(v0), h1 = __float2bfloat16(v1);
            __nv_bfloat16 h2 = __float2bfloat16(v2), h3 = __float2bfloat16(v3);
            __nv_bfloat162 hpA; hpA.x = h0; hpA.y = h1;
            __nv_bfloat162 hpB; hpB.x = h2; hpB.y = h3;
            __nv_bfloat162 lpA;
            lpA.x = __float2bfloat16(v0 - __bfloat162float(h0));
            lpA.y = __float2bfloat16(v1 - __bfloat162float(h1));
            __nv_bfloat162 lpB;
            lpB.x = __float2bfloat16(v2 - __bfloat162float(h2));
            lpB.y = __float2bfloat16(v3 - __bfloat162float(h3));
            *(uint32_t*)(sAhi + r1 * SA + col) = *(uint32_t*)&hpA;
            *(uint32_t*)(sAhi + r2 * SA + col) = *(uint32_t*)&hpB;
            *(uint32_t*)(sAlo + r1 * SA + col) = *(uint32_t*)&lpA;
            *(uint32_t*)(sAlo + r2 * SA + col) = *(uint32_t*)&lpB;
            acc[ma][nb][0] = 0.0f; acc[ma][nb][1] = 0.0f;
            acc[ma][nb][2] = 0.0f; acc[ma][nb][3] = 0.0f;
        }
    __syncthreads();

    // ---- GEMM2: intermediate @ W2 ----
    gemm_pass(sAhi, sAlo, (__nv_bfloat16*)(sh + R_W2H), (__nv_bfloat16*)(sh + R_W2L),
              aBase, bBase, acc);

    if (MODE == 2) __syncthreads();   // about to reuse smem for sF
    float* sF = (float*)sh;           // [128][132]

    #pragma unroll
    for (int ma = 0; ma < 2; ma++)
        #pragma unroll
        for (int nb = 0; nb < 4; nb++) {
            int col = warp_n * 32 + nb * 8 + tig * 2;
            float bs0 = sb2[col], bs1 = sb2[col + 1];
            int r1 = warp_m * 32 + ma * 16 + gid;
            int r2 = r1 + 8;
            float v0 = fmaxf(acc[ma][nb][0] + bs0, 0.0f);
            float v1 = fmaxf(acc[ma][nb][1] + bs1, 0.0f);
            float v2 = fmaxf(acc[ma][nb][2] + bs0, 0.0f);
            float v3 = fmaxf(acc[ma][nb][3] + bs1, 0.0f);
            if (MODE == 1) {
                if (r1 < nr) { float2 p; p.x = v0; p.y = v1;
                    *(float2*)(Of32 + (size_t)(row0 + r1) * 128 + col) = p; }
                if (r2 < nr) { float2 p; p.x = v2; p.y = v3;
                    *(float2*)(Of32 + (size_t)(row0 + r2) * 128 + col) = p; }
            } else {
                float2 p1; p1.x = v0; p1.y = v1;
                float2 p2; p2.x = v2; p2.y = v3;
                *(float2*)(sF + r1 * 132 + col) = p1;
                *(float2*)(sF + r2 * 132 + col) = p2;
            }
        }

    if (MODE == 2) {
        __syncthreads();
        // batch sorted: few segments per tile; 4 threads per column, 32 rows each
        int col = tid & 127, q = tid >> 7;
        int rs = q * 32, re = min(rs + 32, nr);
        float a = 0.0f; int cur = -1;
        for (int r = rs; r < re; r++) {
            int g = sbatch[r];
            if (g != cur) {
                if (cur >= 0) atomicAdd(&g_pool[cur * HIDDEN + col], a);
                cur = g; a = 0.0f;
            }
            a += sF[r * 132 + col];
        }
        if (cur >= 0) atomicAdd(&g_pool[cur * HIDDEN + col], a);
    }
}

// ================= final FC (counts via binary search on sorted batch) =================
__global__ void fc_kernel(const int* __restrict__ batch, const float* __restrict__ Wfc,
                          const float* __restrict__ bfc, float* __restrict__ out) {
    int g = blockIdx.x * blockDim.x + threadIdx.x;
    if (g >= NUM_GRAPHS) return;
    int lo = 0, hi = N_NODES;
    while (lo < hi) { int m = (lo + hi) >> 1; if (batch[m] < g) lo = m + 1; else hi = m; }
    int lb = lo;
    hi = N_NODES;
    while (lo < hi) { int m = (lo + hi) >> 1; if (batch[m] <= g) lo = m + 1; else hi = m; }
    float inv = 1.0f / fmaxf((float)(lo - lb), 1.0f);
    float a0 = 0.0f, a1 = 0.0f;
    const float* row = &g_pool[g * HIDDEN];
    #pragma unroll 4
    for (int k = 0; k < HIDDEN; k++) {
        float v = row[k];
        a0 += v * Wfc[k * 2 + 0];
        a1 += v * Wfc[k * 2 + 1];
    }
    out[g * 2 + 0] = a0 * inv + bfc[0];
    out[g * 2 + 1] = a1 * inv + bfc[1];
}

// ================= launch =================
extern "C" void kernel_launch(void* const* d_in, const int* in_sizes, int n_in,
                              void* d_out, int out_size) {
    const float* x = nullptr;
    const int* ei = nullptr;
    const int* batch = nullptr;
    const float* Ws[4] = {nullptr, nullptr, nullptr, nullptr};
    const float* bs[4] = {nullptr, nullptr, nullptr, nullptr};
    const float* Wfc = nullptr;
    const float* bfc = nullptr;
    int wi = 0, bi = 0;
    for (int i = 0; i < n_in; i++) {
        int sz = in_sizes[i];
        if      (sz == N_NODES * HIDDEN)  x     = (const float*)d_in[i];
        else if (sz == 2 * N_EDGES)       ei    = (const int*)d_in[i];
        else if (sz == N_NODES)           batch = (const int*)d_in[i];
        else if (sz == HIDDEN * HIDDEN)   { if (wi < 4) Ws[wi++] = (const float*)d_in[i]; }
        else if (sz == HIDDEN)            { if (bi < 4) bs[bi++] = (const float*)d_in[i]; }
        else if (sz == HIDDEN * 2)        Wfc   = (const float*)d_in[i];
        else if (sz == 2)                 bfc   = (const float*)d_in[i];
    }
    float* out = (float*)d_out;

    __nv_bfloat16 *Ahi, *Alo, *Whi0, *Wlo0;
    float *H;
    cudaGetSymbolAddress((void**)&Ahi,  g_Ahi);
    cudaGetSymbolAddress((void**)&Alo,  g_Alo);
    cudaGetSymbolAddress((void**)&H,    g_H);
    cudaGetSymbolAddress((void**)&Whi0, g_Whi);
    cudaGetSymbolAddress((void**)&Wlo0, g_Wlo);

    cudaFuncSetAttribute(mlp_mma<1>, cudaFuncAttributeMaxDynamicSharedMemorySize, MLP_SMEM);
    cudaFuncSetAttribute(mlp_mma<2>, cudaFuncAttributeMaxDynamicSharedMemorySize, MLP_SMEM);

    // prep (zero + weight conversion) + CSR build
    prep_kernel<<<256, 256>>>(Ws[0], Ws[1], Ws[2], Ws[3]);
    hist_kernel<<<(N_EDGES / 4 + 255) / 256, 256>>>(ei);
    scan_kernel<<<1, 1024>>>();
    fill_kernel<<<(N_EDGES / 4 + 255) / 256, 256>>>(ei);

    int agg_blocks  = (N_NODES * 32 + 255) / 256;
    int mlp_blocks  = (N_NODES + 127) / 128;

    // Layer 1 (agg -> fused MLP -> fp32 H)
    agg_conv_kernel<<<agg_blocks, 256>>>((const float4*)x, Ahi, Alo);
    mlp_mma<1><<<mlp_blocks, 512, MLP_SMEM>>>(Ahi, Alo,
        Whi0 + 0 * 16384, Wlo0 + 0 * 16384, bs[0],
        Whi0 + 1 * 16384, Wlo0 + 1 * 16384, bs[1], H, nullptr);

    // Layer 2 (agg -> fused MLP -> fused mean-pool)
    agg_conv_kernel<<<agg_blocks, 256>>>((const float4*)H, Ahi, Alo);
    mlp_mma<2><<<mlp_blocks, 512, MLP_SMEM>>>(Ahi, Alo,
        Whi0 + 2 * 16384, Wlo0 + 2 * 16384, bs[2],
        Whi0 + 3 * 16384, Wlo0 + 3 * 16384, bs[3], nullptr, batch);

    // FC
    fc_kernel<<<(NUM_GRAPHS + 255) / 256, 256>>>(batch, Wfc, bfc, out);
}

// round 11
// speedup vs baseline: 1.3226x; 1.3226x over previous
#include <cuda_runtime.h>
#include <cuda_bf16.h>
#include <cstdint>

#define N_NODES    50000
#define N_EDGES    800000
#define HIDDEN     128
#define NUM_GRAPHS 512

// ================= scratch (static device globals; no allocation) =================
__device__ __nv_bfloat16 g_Ahi[N_NODES * HIDDEN];
__device__ __nv_bfloat16 g_Alo[N_NODES * HIDDEN];
__device__ __nv_bfloat16 g_Mhi[N_NODES * HIDDEN];
__device__ __nv_bfloat16 g_Mlo[N_NODES * HIDDEN];
__device__ float         g_H[N_NODES * HIDDEN];
__device__ __nv_bfloat16 g_Whi[4][HIDDEN * HIDDEN];   // transposed: [n][k]
__device__ __nv_bfloat16 g_Wlo[4][HIDDEN * HIDDEN];
__device__ int    g_deg[N_NODES];
__device__ int    g_rowptr[N_NODES + 1];
__device__ int    g_cursor[N_NODES];
__device__ int    g_col[N_EDGES];
__device__ float  g_pool[NUM_GRAPHS * HIDDEN];

// ================= prep: zero scratch + convert all 4 weights (one launch) =========
__global__ void prep_kernel(const float* __restrict__ W0, const float* __restrict__ W1,
                            const float* __restrict__ W2, const float* __restrict__ W3) {
    int i = blockIdx.x * blockDim.x + threadIdx.x;
    int st = gridDim.x * blockDim.x;
    for (int j = i; j < N_NODES; j += st) g_deg[j] = 0;
    for (int j = i; j < NUM_GRAPHS * HIDDEN; j += st) g_pool[j] = 0.0f;
    const float* Wt[4] = {W0, W1, W2, W3};
    #pragma unroll
    for (int q = 0; q < 4; q++) {
        const float* W = Wt[q];
        for (int j = i; j < HIDDEN * HIDDEN; j += st) {
            int k = j >> 7, n = j & 127;           // W[k][n] row-major
            float v = W[j];
            __nv_bfloat16 h = __float2bfloat16(v);
            g_Whi[q][n * 128 + k] = h;             // B[n][k] = W[k][n]
            g_Wlo[q][n * 128 + k] = __float2bfloat16(v - __bfloat162float(h));
        }
    }
}

// ================= degree histogram (1 edge / thread — measured faster) =============
__global__ void hist_kernel(const int* __restrict__ ei) {
    int e = blockIdx.x * blockDim.x + threadIdx.x;
    if (e < N_EDGES) {
        int dst = ei[N_EDGES + e];
        if ((unsigned)dst < (unsigned)N_NODES) atomicAdd(&g_deg[dst], 1);
    }
}

// ================= exclusive scan (single block, int4 per thread) =================
__global__ void scan_kernel() {
    __shared__ int warp_sums[32];
    __shared__ int s_carry;
    int tid = threadIdx.x, lane = tid & 31, w = tid >> 5;
    if (tid == 0) { s_carry = 0; g_rowptr[0] = 0; }
    __syncthreads();
    const int N4 = N_NODES / 4;   // 12500
    for (int base = 0; base < N4; base += 1024) {
        int i4 = base + tid;
        int4 v = make_int4(0, 0, 0, 0);
        if (i4 < N4) v = ((const int4*)g_deg)[i4];
        int s0 = v.x, s1 = s0 + v.y, s2 = s1 + v.z, s3 = s2 + v.w;
        int tot = s3;
        int inc = tot;
        #pragma unroll
        for (int o = 1; o < 32; o <<= 1) {
            int t = __shfl_up_sync(0xFFFFFFFFu, inc, o);
            if (lane >= o) inc += t;
        }
        if (lane == 31) warp_sums[w] = inc;
        __syncthreads();
        if (w == 0) {
            int s = warp_sums[lane];
            int si = s;
            #pragma unroll
            for (int o = 1; o < 32; o <<= 1) {
                int t = __shfl_up_sync(0xFFFFFFFFu, si, o);
                if (lane >= o) si += t;
            }
            warp_sums[lane] = si - s;
        }
        __syncthreads();
        int off = s_carry + warp_sums[w] + (inc - tot);
        if (i4 < N4) {
            int b = i4 * 4;
            ((int4*)g_cursor)[i4] = make_int4(off, off + s0, off + s1, off + s2);
            g_rowptr[b + 1] = off + s0;
            g_rowptr[b + 2] = off + s1;
            g_rowptr[b + 3] = off + s2;
            g_rowptr[b + 4] = off + s3;
        }
        __syncthreads();
        int lastT = min(1024, N4 - base) - 1;
        if (tid == lastT) s_carry = off + tot;
        __syncthreads();
    }
}

// ================= CSR fill (1 edge / thread — measured faster) =================
__global__ void fill_kernel(const int* __restrict__ ei) {
    int e = blockIdx.x * blockDim.x + threadIdx.x;
    if (e < N_EDGES) {
        int src = ei[e];
        int dst = ei[N_EDGES + e];
        if ((unsigned)dst < (unsigned)N_NODES && (unsigned)src < (unsigned)N_NODES) {
            int pos = atomicAdd(&g_cursor[dst], 1);
            g_col[pos] = src;
        }
    }
}

// ================= aggregation + split-bf16 conversion =================
__global__ void agg_conv_kernel(const float4* __restrict__ in,
                                __nv_bfloat16* __restrict__ Ohi,
                                __nv_bfloat16* __restrict__ Olo) {
    int gw = (blockIdx.x * blockDim.x + threadIdx.x) >> 5;
    if (gw >= N_NODES) return;
    int lane = threadIdx.x & 31;
    float4 acc = in[gw * 32 + lane];
    int s = g_rowptr[gw], e = g_rowptr[gw + 1];
    int j = (s < e) ? g_col[s] : 0;
    for (int p = s; p < e; p++) {
        int jn = (p + 1 < e) ? g_col[p + 1] : 0;
        float4 v = in[j * 32 + lane];
        acc.x += v.x; acc.y += v.y; acc.z += v.z; acc.w += v.w;
        j = jn;
    }
    __nv_bfloat16 hx = __float2bfloat16(acc.x), hy = __float2bfloat16(acc.y);
    __nv_bfloat16 hz = __float2bfloat16(acc.z), hw = __float2bfloat16(acc.w);
    __nv_bfloat162 hp0; hp0.x = hx; hp0.y = hy;
    __nv_bfloat162 hp1; hp1.x = hz; hp1.y = hw;
    __nv_bfloat162 lp0; lp0.x = __float2bfloat16(acc.x - __bfloat162float(hx));
                        lp0.y = __float2bfloat16(acc.y - __bfloat162float(hy));
    __nv_bfloat162 lp1; lp1.x = __float2bfloat16(acc.z - __bfloat162float(hz));
                        lp1.y = __float2bfloat16(acc.w - __bfloat162float(hw));
    uint2 hv; hv.x = *(uint32_t*)&hp0; hv.y = *(uint32_t*)&hp1;
    uint2 lv; lv.x = *(uint32_t*)&lp0; lv.y = *(uint32_t*)&lp1;
    *(uint2*)(Ohi + (size_t)gw * 128 + lane * 4) = hv;
    *(uint2*)(Olo + (size_t)gw * 128 + lane * 4) = lv;
}

// ================= HMMA GEMM: C = relu(A[64tile,128] @ W + b) =================
// 64-row tiles, 256 threads, ~105KB smem -> 2 CTAs/SM for cross-CTA overlap.
// MODE 0: output split bf16 hi/lo   MODE 1: output fp32   MODE 2: fused mean-pool
#define SA 136                       // padded smem row stride (elements)
static constexpr int R_AHI  = 0;                        // 64*136*2  = 17408
static constexpr int R_ALO  = 17408;
static constexpr int R_WHI  = 34816;                    // 128*136*2 = 34816
static constexpr int R_WLO  = 69632;
static constexpr int OFF_BIAS  = 104448;                // 512
static constexpr int OFF_BATCH = 104960;                // 256
static constexpr int GEMM_SMEM = 105472;

__device__ __forceinline__ void mma16816(float* c,
    uint32_t a0, uint32_t a1, uint32_t a2, uint32_t a3, uint32_t b0, uint32_t b1) {
    asm volatile(
        "mma.sync.aligned.m16n8k16.row.col.f32.bf16.bf16.f32 "
        "{%0,%1,%2,%3}, {%4,%5,%6,%7}, {%8,%9}, {%0,%1,%2,%3};"
        : "+f"(c[0]), "+f"(c[1]), "+f"(c[2]), "+f"(c[3])
        : "r"(a0), "r"(a1), "r"(a2), "r"(a3), "r"(b0), "r"(b1));
}

template <int MODE>
__global__ void __launch_bounds__(256) gemm_mma(
    const __nv_bfloat16* __restrict__ Ahi, const __nv_bfloat16* __restrict__ Alo,
    const __nv_bfloat16* __restrict__ Whi, const __nv_bfloat16* __restrict__ Wlo,
    const float* __restrict__ bias,
    __nv_bfloat16* __restrict__ Ohi, __nv_bfloat16* __restrict__ Olo,
    float* __restrict__ Of32,
    const int* __restrict__ batch)
{
    extern __shared__ char sh[];
    __nv_bfloat16* sAhi = (__nv_bfloat16*)(sh + R_AHI);
    __nv_bfloat16* sAlo = (__nv_bfloat16*)(sh + R_ALO);
    __nv_bfloat16* sWhi = (__nv_bfloat16*)(sh + R_WHI);
    __nv_bfloat16* sWlo = (__nv_bfloat16*)(sh + R_WLO);
    float* sbias  = (float*)(sh + OFF_BIAS);
    int*   sbatch = (int*)(sh + OFF_BATCH);

    int tid = threadIdx.x;
    int row0 = blockIdx.x * 64;
    int nr = min(64, N_NODES - row0);

    if (tid < 128) {
        sbias[tid] = bias[tid];
        if (MODE == 2 && tid < 64) sbatch[tid] = (tid < nr) ? batch[row0 + tid] : -1;
    }

    // ---- stage tiles: A hi/lo (64 rows, guarded) + W hi/lo (128 rows) ----
    const uint4 z = make_uint4(0, 0, 0, 0);
    #pragma unroll
    for (int it = 0; it < 4; it++) {         // A tiles: 1024 uint4 each
        int idx = tid + it * 256;
        int r = idx >> 4, c = idx & 15;
        uint4 vh, vl;
        if (r < nr) {
            vh = *(const uint4*)(Ahi + (size_t)(row0 + r) * 128 + c * 8);
            vl = *(const uint4*)(Alo + (size_t)(row0 + r) * 128 + c * 8);
        } else { vh = z; vl = z; }
        *(uint4*)(sAhi + r * SA + c * 8) = vh;
        *(uint4*)(sAlo + r * SA + c * 8) = vl;
    }
    #pragma unroll
    for (int it = 0; it < 8; it++) {         // W tiles: 2048 uint4 each
        int idx = tid + it * 256;
        int r = idx >> 4, c = idx & 15;
        uint4 wh = *(const uint4*)(Whi + (size_t)r * 128 + c * 8);
        uint4 wl = *(const uint4*)(Wlo + (size_t)r * 128 + c * 8);
        *(uint4*)(sWhi + r * SA + c * 8) = wh;
        *(uint4*)(sWlo + r * SA + c * 8) = wl;
    }
    __syncthreads();

    int wid = tid >> 5, lid = tid & 31;
    int warp_m = wid >> 2, warp_n = wid & 3;   // 2x4 warp grid, warp tile 32x32
    int gid = lid >> 2, tig = lid & 3;

    float acc[2][4][4];
    #pragma unroll
    for (int ma = 0; ma < 2; ma++)
        #pragma unroll
        for (int nb = 0; nb < 4; nb++)
            #pragma unroll
            for (int q = 0; q < 4; q++) acc[ma][nb][q] = 0.0f;

    int aBase = (warp_m * 32 + gid) * SA + tig * 2;
    int bBase = (warp_n * 32 + gid) * SA + tig * 2;

    #pragma unroll
    for (int kk = 0; kk < 8; kk++) {
        int k0 = kk * 16;
        uint32_t ah[2][4], al[2][4];
        #pragma unroll
        for (int ma = 0; ma < 2; ma++) {
            int b = aBase + ma * 16 * SA + k0;
            ah[ma][0] = *(const uint32_t*)(sAhi + b);
            ah[ma][1] = *(const uint32_t*)(sAhi + b + 8 * SA);
            ah[ma][2] = *(const uint32_t*)(sAhi + b + 8);
            ah[ma][3] = *(const uint32_t*)(sAhi + b + 8 * SA + 8);
            al[ma][0] = *(const uint32_t*)(sAlo + b);
            al[ma][1] = *(const uint32_t*)(sAlo + b + 8 * SA);
            al[ma][2] = *(const uint32_t*)(sAlo + b + 8);
            al[ma][3] = *(const uint32_t*)(sAlo + b + 8 * SA + 8);
        }
        uint32_t bh[4][2], bl[4][2];
        #pragma unroll
        for (int nb = 0; nb < 4; nb++) {
            int b = bBase + nb * 8 * SA + k0;
            bh[nb][0] = *(const uint32_t*)(sWhi + b);
            bh[nb][1] = *(const uint32_t*)(sWhi + b + 8);
            bl[nb][0] = *(const uint32_t*)(sWlo + b);
            bl[nb][1] = *(const uint32_t*)(sWlo + b + 8);
        }
        #pragma unroll
        for (int ma = 0; ma < 2; ma++)
            #pragma unroll
            for (int nb = 0; nb < 4; nb++) {
                mma16816(acc[ma][nb], ah[ma][0], ah[ma][1], ah[ma][2], ah[ma][3], bh[nb][0], bh[nb][1]);
                mma16816(acc[ma][nb], ah[ma][0], ah[ma][1], ah[ma][2], ah[ma][3], bl[nb][0], bl[nb][1]);
                mma16816(acc[ma][nb], al[ma][0], al[ma][1], al[ma][2], al[ma][3], bh[nb][0], bh[nb][1]);
            }
    }

    if (MODE == 2) __syncthreads();   // tiles dead; about to reuse smem for sF
    float* sF = (float*)sh;           // [64][132]

    #pragma unroll
    for (int ma = 0; ma < 2; ma++)
        #pragma unroll
        for (int nb = 0; nb < 4; nb++) {
            int col = warp_n * 32 + nb * 8 + tig * 2;
            float bs0 = sbias[col], bs1 = sbias[col + 1];
            int r1 = warp_m * 32 + ma * 16 + gid;
            int r2 = r1 + 8;
            float v0 = fmaxf(acc[ma][nb][0] + bs0, 0.0f);
            float v1 = fmaxf(acc[ma][nb][1] + bs1, 0.0f);
            float v2 = fmaxf(acc[ma][nb][2] + bs0, 0.0f);
            float v3 = fmaxf(acc[ma][nb][3] + bs1, 0.0f);
            if (MODE == 0) {
                if (r1 < nr) {
                    __nv_bfloat16 h0 = __float2bfloat16(v0), h1 = __float2bfloat16(v1);
                    __nv_bfloat162 hp; hp.x = h0; hp.y = h1;
                    __nv_bfloat162 lp;
                    lp.x = __float2bfloat16(v0 - __bfloat162float(h0));
                    lp.y = __float2bfloat16(v1 - __bfloat162float(h1));
                    *(uint32_t*)(Ohi + (size_t)(row0 + r1) * 128 + col) = *(uint32_t*)&hp;
                    *(uint32_t*)(Olo + (size_t)(row0 + r1) * 128 + col) = *(uint32_t*)&lp;
                }
                if (r2 < nr) {
                    __nv_bfloat16 h2 = __float2bfloat16(v2), h3 = __float2bfloat16(v3);
                    __nv_bfloat162 hp; hp.x = h2; hp.y = h3;
                    __nv_bfloat162 lp;
                    lp.x = __float2bfloat16(v2 - __bfloat162float(h2));
                    lp.y = __float2bfloat16(v3 - __bfloat162float(h3));
                    *(uint32_t*)(Ohi + (size_t)(row0 + r2) * 128 + col) = *(uint32_t*)&hp;
                    *(uint32_t*)(Olo + (size_t)(row0 + r2) * 128 + col) = *(uint32_t*)&lp;
                }
            } else if (MODE == 1) {
                if (r1 < nr) { float2 p; p.x = v0; p.y = v1;
                    *(float2*)(Of32 + (size_t)(row0 + r1) * 128 + col) = p; }
                if (r2 < nr) { float2 p; p.x = v2; p.y = v3;
                    *(float2*)(Of32 + (size_t)(row0 + r2) * 128 + col) = p; }
            } else {
                float2 p1; p1.x = v0; p1.y = v1;
                float2 p2; p2.x = v2; p2.y = v3;
                *(float2*)(sF + r1 * 132 + col) = p1;
                *(float2*)(sF + r2 * 132 + col) = p2;
            }
        }

    if (MODE == 2) {
        __syncthreads();
        // batch sorted: few segments per tile; 2 threads per column, 32 rows each
        int col = tid & 127, q = tid >> 7;        // q in {0,1}
        int rs = q * 32, re = min(rs + 32, nr);
        float a = 0.0f; int cur = -1;
        for (int r = rs; r < re; r++) {
            int g = sbatch[r];
            if (g != cur) {
                if (cur >= 0) atomicAdd(&g_pool[cur * HIDDEN + col], a);
                cur = g; a = 0.0f;
            }
            a += sF[r * 132 + col];
        }
        if (cur >= 0) atomicAdd(&g_pool[cur * HIDDEN + col], a);
    }
}

// ================= final FC (counts via binary search on sorted batch) =================
__global__ void fc_kernel(const int* __restrict__ batch, const float* __restrict__ Wfc,
                          const float* __restrict__ bfc, float* __restrict__ out) {
    int g = blockIdx.x * blockDim.x + threadIdx.x;
    if (g >= NUM_GRAPHS) return;
    int lo = 0, hi = N_NODES;
    while (lo < hi) { int m = (lo + hi) >> 1; if (batch[m] < g) lo = m + 1; else hi = m; }
    int lb = lo;
    hi = N_NODES;
    while (lo < hi) { int m = (lo + hi) >> 1; if (batch[m] <= g) lo = m + 1; else hi = m; }
    float inv = 1.0f / fmaxf((float)(lo - lb), 1.0f);
    float a0 = 0.0f, a1 = 0.0f;
    const float* row = &g_pool[g * HIDDEN];
    #pragma unroll 4
    for (int k = 0; k < HIDDEN; k++) {
        float v = row[k];
        a0 += v * Wfc[k * 2 + 0];
        a1 += v * Wfc[k * 2 + 1];
    }
    out[g * 2 + 0] = a0 * inv + bfc[0];
    out[g * 2 + 1] = a1 * inv + bfc[1];
}

// ================= launch =================
extern "C" void kernel_launch(void* const* d_in, const int* in_sizes, int n_in,
                              void* d_out, int out_size) {
    const float* x = nullptr;
    const int* ei = nullptr;
    const int* batch = nullptr;
    const float* Ws[4] = {nullptr, nullptr, nullptr, nullptr};
    const float* bs[4] = {nullptr, nullptr, nullptr, nullptr};
    const float* Wfc = nullptr;
    const float* bfc = nullptr;
    int wi = 0, bi = 0;
    for (int i = 0; i < n_in; i++) {
        int sz = in_sizes[i];
        if      (sz == N_NODES * HIDDEN)  x     = (const float*)d_in[i];
        else if (sz == 2 * N_EDGES)       ei    = (const int*)d_in[i];
        else if (sz == N_NODES)           batch = (const int*)d_in[i];
        else if (sz == HIDDEN * HIDDEN)   { if (wi < 4) Ws[wi++] = (const float*)d_in[i]; }
        else if (sz == HIDDEN)            { if (bi < 4) bs[bi++] = (const float*)d_in[i]; }
        else if (sz == HIDDEN * 2)        Wfc   = (const float*)d_in[i];
        else if (sz == 2)                 bfc   = (const float*)d_in[i];
    }
    float* out = (float*)d_out;

    __nv_bfloat16 *Ahi, *Alo, *Mhi, *Mlo, *Whi0, *Wlo0;
    float *H;
    cudaGetSymbolAddress((void**)&Ahi,  g_Ahi);
    cudaGetSymbolAddress((void**)&Alo,  g_Alo);
    cudaGetSymbolAddress((void**)&Mhi,  g_Mhi);
    cudaGetSymbolAddress((void**)&Mlo,  g_Mlo);
    cudaGetSymbolAddress((void**)&H,    g_H);
    cudaGetSymbolAddress((void**)&Whi0, g_Whi);
    cudaGetSymbolAddress((void**)&Wlo0, g_Wlo);

    cudaFuncSetAttribute(gemm_mma<0>, cudaFuncAttributeMaxDynamicSharedMemorySize, GEMM_SMEM);
    cudaFuncSetAttribute(gemm_mma<1>, cudaFuncAttributeMaxDynamicSharedMemorySize, GEMM_SMEM);
    cudaFuncSetAttribute(gemm_mma<2>, cudaFuncAttributeMaxDynamicSharedMemorySize, GEMM_SMEM);

    // prep (zero + weight conversion) + CSR build
    prep_kernel<<<256, 256>>>(Ws[0], Ws[1], Ws[2], Ws[3]);
    hist_kernel<<<(N_EDGES + 255) / 256, 256>>>(ei);
    scan_kernel<<<1, 1024>>>();
    fill_kernel<<<(N_EDGES + 255) / 256, 256>>>(ei);

    int agg_blocks  = (N_NODES * 32 + 255) / 256;
    int gemm_blocks = (N_NODES + 63) / 64;

    // Layer 1
    agg_conv_kernel<<<agg_blocks, 256>>>((const float4*)x, Ahi, Alo);
    gemm_mma<0><<<gemm_blocks, 256, GEMM_SMEM>>>(Ahi, Alo, Whi0 + 0 * 16384, Wlo0 + 0 * 16384,
                                                 bs[0], Mhi, Mlo, nullptr, nullptr);
    gemm_mma<1><<<gemm_blocks, 256, GEMM_SMEM>>>(Mhi, Mlo, Whi0 + 1 * 16384, Wlo0 + 1 * 16384,
                                                 bs[1], nullptr, nullptr, H, nullptr);
    // Layer 2
    agg_conv_kernel<<<agg_blocks, 256>>>((const float4*)H, Ahi, Alo);
    gemm_mma<0><<<gemm_blocks, 256, GEMM_SMEM>>>(Ahi, Alo, Whi0 + 2 * 16384, Wlo0 + 2 * 16384,
                                                 bs[2], Mhi, Mlo, nullptr, nullptr);
    gemm_mma<2><<<gemm_blocks, 256, GEMM_SMEM>>>(Mhi, Mlo, Whi0 + 3 * 16384, Wlo0 + 3 * 16384,
                                                 bs[3], nullptr, nullptr, nullptr, batch);
    // FC
    fc_kernel<<<(NUM_GRAPHS + 255) / 256, 256>>>(batch, Wfc, bfc, out);
}

// round 14
// speedup vs baseline: 1.3585x; 1.0271x over previous
#include <cuda_runtime.h>
#include <cuda_bf16.h>
#include <cstdint>

#define N_NODES    50000
#define N_EDGES    800000
#define HIDDEN     128
#define NUM_GRAPHS 512

// ================= scratch (static device globals; no allocation) =================
__device__ __nv_bfloat16 g_Ahi[N_NODES * HIDDEN];
__device__ __nv_bfloat16 g_Alo[N_NODES * HIDDEN];
__device__ __nv_bfloat16 g_Mhi[N_NODES * HIDDEN];
__device__ __nv_bfloat16 g_Mlo[N_NODES * HIDDEN];
__device__ float         g_H[N_NODES * HIDDEN];
__device__ __nv_bfloat16 g_Whi[4][HIDDEN * HIDDEN];   // transposed: [n][k]
__device__ __nv_bfloat16 g_Wlo[4][HIDDEN * HIDDEN];
__device__ int    g_deg[N_NODES];
__device__ int    g_rowptr[N_NODES + 1];
__device__ int    g_cursor[N_NODES];
__device__ int    g_col[N_EDGES];
__device__ float  g_pool[NUM_GRAPHS * HIDDEN];

// ================= zero degrees (must precede hist) =================
__global__ void zero_kernel() {
    int i = blockIdx.x * blockDim.x + threadIdx.x;
    int st = gridDim.x * blockDim.x;
    for (int j = i; j < N_NODES; j += st) g_deg[j] = 0;
}

// ================= degree histogram (1 edge / thread) =================
__global__ void hist_kernel(const int* __restrict__ ei) {
    int e = blockIdx.x * blockDim.x + threadIdx.x;
    if (e < N_EDGES) {
        int dst = ei[N_EDGES + e];
        if ((unsigned)dst < (unsigned)N_NODES) atomicAdd(&g_deg[dst], 1);
    }
}

// ====== scan (block 0) + weight conversion / pool zero (blocks 1..128) ======
// Block 0 is the latency-bound serial scan; the other 147 SMs were idle during
// it, so the prep work rides along for free.
__global__ void scan_prep_kernel(const float* __restrict__ W0, const float* __restrict__ W1,
                                 const float* __restrict__ W2, const float* __restrict__ W3) {
    if (blockIdx.x != 0) {
        int idx = (blockIdx.x - 1) * 1024 + threadIdx.x;   // 0 .. 131071
        if (idx < 4 * HIDDEN * HIDDEN) {
            int q = idx >> 14, j = idx & 16383;
            const float* W = (q == 0) ? W0 : (q == 1) ? W1 : (q == 2) ? W2 : W3;
            int k = j >> 7, n = j & 127;           // W[k][n] row-major
            float v = W[j];
            __nv_bfloat16 h = __float2bfloat16(v);
            g_Whi[q][n * 128 + k] = h;             // B[n][k] = W[k][n]
            g_Wlo[q][n * 128 + k] = __float2bfloat16(v - __bfloat162float(h));
        } else {
            int j = idx - 4 * HIDDEN * HIDDEN;
            if (j < NUM_GRAPHS * HIDDEN) g_pool[j] = 0.0f;
        }
        return;
    }
    // ---- block 0: exclusive scan over g_deg (int4 per thread) ----
    __shared__ int warp_sums[32];
    __shared__ int s_carry;
    int tid = threadIdx.x, lane = tid & 31, w = tid >> 5;
    if (tid == 0) { s_carry = 0; g_rowptr[0] = 0; }
    __syncthreads();
    const int N4 = N_NODES / 4;   // 12500
    for (int base = 0; base < N4; base += 1024) {
        int i4 = base + tid;
        int4 v = make_int4(0, 0, 0, 0);
        if (i4 < N4) v = ((const int4*)g_deg)[i4];
        int s0 = v.x, s1 = s0 + v.y, s2 = s1 + v.z, s3 = s2 + v.w;
        int tot = s3;
        int inc = tot;
        #pragma unroll
        for (int o = 1; o < 32; o <<= 1) {
            int t = __shfl_up_sync(0xFFFFFFFFu, inc, o);
            if (lane >= o) inc += t;
        }
        if (lane == 31) warp_sums[w] = inc;
        __syncthreads();
        if (w == 0) {
            int s = warp_sums[lane];
            int si = s;
            #pragma unroll
            for (int o = 1; o < 32; o <<= 1) {
                int t = __shfl_up_sync(0xFFFFFFFFu, si, o);
                if (lane >= o) si += t;
            }
            warp_sums[lane] = si - s;
        }
        __syncthreads();
        int off = s_carry + warp_sums[w] + (inc - tot);
        if (i4 < N4) {
            int b = i4 * 4;
            ((int4*)g_cursor)[i4] = make_int4(off, off + s0, off + s1, off + s2);
            g_rowptr[b + 1] = off + s0;
            g_rowptr[b + 2] = off + s1;
            g_rowptr[b + 3] = off + s2;
            g_rowptr[b + 4] = off + s3;
        }
        __syncthreads();
        int lastT = min(1024, N4 - base) - 1;
        if (tid == lastT) s_carry = off + tot;
        __syncthreads();
    }
}

// ================= CSR fill (1 edge / thread) =================
__global__ void fill_kernel(const int* __restrict__ ei) {
    int e = blockIdx.x * blockDim.x + threadIdx.x;
    if (e < N_EDGES) {
        int src = ei[e];
        int dst = ei[N_EDGES + e];
        if ((unsigned)dst < (unsigned)N_NODES && (unsigned)src < (unsigned)N_NODES) {
            int pos = atomicAdd(&g_cursor[dst], 1);
            g_col[pos] = src;
        }
    }
}

// ================= aggregation + split-bf16 conversion =================
__global__ void agg_conv_kernel(const float4* __restrict__ in,
                                __nv_bfloat16* __restrict__ Ohi,
                                __nv_bfloat16* __restrict__ Olo) {
    int gw = (blockIdx.x * blockDim.x + threadIdx.x) >> 5;
    if (gw >= N_NODES) return;
    int lane = threadIdx.x & 31;
    float4 acc = in[gw * 32 + lane];
    int s = g_rowptr[gw], e = g_rowptr[gw + 1];
    int j = (s < e) ? g_col[s] : 0;
    for (int p = s; p < e; p++) {
        int jn = (p + 1 < e) ? g_col[p + 1] : 0;
        float4 v = in[j * 32 + lane];
        acc.x += v.x; acc.y += v.y; acc.z += v.z; acc.w += v.w;
        j = jn;
    }
    __nv_bfloat16 hx = __float2bfloat16(acc.x), hy = __float2bfloat16(acc.y);
    __nv_bfloat16 hz = __float2bfloat16(acc.z), hw = __float2bfloat16(acc.w);
    __nv_bfloat162 hp0; hp0.x = hx; hp0.y = hy;
    __nv_bfloat162 hp1; hp1.x = hz; hp1.y = hw;
    __nv_bfloat162 lp0; lp0.x = __float2bfloat16(acc.x - __bfloat162float(hx));
                        lp0.y = __float2bfloat16(acc.y - __bfloat162float(hy));
    __nv_bfloat162 lp1; lp1.x = __float2bfloat16(acc.z - __bfloat162float(hz));
                        lp1.y = __float2bfloat16(acc.w - __bfloat162float(hw));
    uint2 hv; hv.x = *(uint32_t*)&hp0; hv.y = *(uint32_t*)&hp1;
    uint2 lv; lv.x = *(uint32_t*)&lp0; lv.y = *(uint32_t*)&lp1;
    *(uint2*)(Ohi + (size_t)gw * 128 + lane * 4) = hv;
    *(uint2*)(Olo + (size_t)gw * 128 + lane * 4) = lv;
}

// ================= HMMA GEMM: C = relu(A[64tile,128] @ W + b) =================
// 64-row tiles, 256 threads, ~105KB smem -> 2 CTAs/SM.
// cp.async staging + ldmatrix.x4 fragment loads.
// MODE 0: output split bf16 hi/lo   MODE 1: output fp32   MODE 2: fused mean-pool
#define SA 136                       // padded smem row stride (elements); 272B rows
static constexpr int R_AHI  = 0;                        // 64*136*2  = 17408
static constexpr int R_ALO  = 17408;
static constexpr int R_WHI  = 34816;                    // 128*136*2 = 34816
static constexpr int R_WLO  = 69632;
static constexpr int OFF_BIAS  = 104448;                // 512
static constexpr int OFF_BATCH = 104960;                // 256
static constexpr int GEMM_SMEM = 105472;

__device__ __forceinline__ void mma16816(float* c,
    uint32_t a0, uint32_t a1, uint32_t a2, uint32_t a3, uint32_t b0, uint32_t b1) {
    asm volatile(
        "mma.sync.aligned.m16n8k16.row.col.f32.bf16.bf16.f32 "
        "{%0,%1,%2,%3}, {%4,%5,%6,%7}, {%8,%9}, {%0,%1,%2,%3};"
        : "+f"(c[0]), "+f"(c[1]), "+f"(c[2]), "+f"(c[3])
        : "r"(a0), "r"(a1), "r"(a2), "r"(a3), "r"(b0), "r"(b1));
}
__device__ __forceinline__ void ldsm_x4(uint32_t* r, uint32_t addr) {
    asm volatile("ldmatrix.sync.aligned.m8n8.x4.shared.b16 {%0,%1,%2,%3}, [%4];"
        : "=r"(r[0]), "=r"(r[1]), "=r"(r[2]), "=r"(r[3]) : "r"(addr));
}
__device__ __forceinline__ void cpasync16(uint32_t dst, const void* src, int szBytes) {
    asm volatile("cp.async.cg.shared.global [%0], [%1], 16, %2;"
        :: "r"(dst), "l"(src), "r"(szBytes));
}

template <int MODE>
__global__ void __launch_bounds__(256) gemm_mma(
    const __nv_bfloat16* __restrict__ Ahi, const __nv_bfloat16* __restrict__ Alo,
    const __nv_bfloat16* __restrict__ Whi, const __nv_bfloat16* __restrict__ Wlo,
    const float* __restrict__ bias,
    __nv_bfloat16* __restrict__ Ohi, __nv_bfloat16* __restrict__ Olo,
    float* __restrict__ Of32,
    const int* __restrict__ batch)
{
    extern __shared__ char sh[];
    float* sbias  = (float*)(sh + OFF_BIAS);
    int*   sbatch = (int*)(sh + OFF_BATCH);
    uint32_t shb = (uint32_t)__cvta_generic_to_shared(sh);

    int tid = threadIdx.x;
    int row0 = blockIdx.x * 64;
    int nr = min(64, N_NODES - row0);

    if (tid < 128) {
        sbias[tid] = bias[tid];
        if (MODE == 2 && tid < 64) sbatch[tid] = (tid < nr) ? batch[row0 + tid] : -1;
    }

    // ---- stage tiles via cp.async: A hi/lo (zfill OOB rows) + W hi/lo ----
    #pragma unroll
    for (int it = 0; it < 4; it++) {         // A tiles: 1024 x 16B each
        int idx = tid + it * 256;
        int r = idx >> 4, c = idx & 15;
        int sz = (r < nr) ? 16 : 0;
        int rs = (r < nr) ? r : 0;           // keep address in-bounds
        cpasync16(shb + R_AHI + (r * SA + c * 8) * 2,
                  Ahi + (size_t)(row0 + rs) * 128 + c * 8, sz);
        cpasync16(shb + R_ALO + (r * SA + c * 8) * 2,
                  Alo + (size_t)(row0 + rs) * 128 + c * 8, sz);
    }
    #pragma unroll
    for (int it = 0; it < 8; it++) {         // W tiles: 2048 x 16B each
        int idx = tid + it * 256;
        int r = idx >> 4, c = idx & 15;
        cpasync16(shb + R_WHI + (r * SA + c * 8) * 2, Whi + (size_t)r * 128 + c * 8, 16);
        cpasync16(shb + R_WLO + (r * SA + c * 8) * 2, Wlo + (size_t)r * 128 + c * 8, 16);
    }
    asm volatile("cp.async.commit_group;");
    asm volatile("cp.async.wait_group 0;");
    __syncthreads();

    int wid = tid >> 5, lid = tid & 31;
    int warp_m = wid >> 2, warp_n = wid & 3;   // 2x4 warp grid, warp tile 32x32
    int gid = lid >> 2, tig = lid & 3;

    // ldmatrix lane address offsets (bytes)
    uint32_t aLane = ((lid & 15) * SA + (lid >> 4) * 8) * 2;
    uint32_t bLane = (((lid & 7) + ((lid >> 4) << 3)) * SA + ((lid >> 3) & 1) * 8) * 2;
    uint32_t aRowB = (uint32_t)(warp_m * 32) * SA * 2;
    uint32_t bRowB = (uint32_t)(warp_n * 32) * SA * 2;

    float acc[2][4][4];
    #pragma unroll
    for (int ma = 0; ma < 2; ma++)
        #pragma unroll
        for (int nb = 0; nb < 4; nb++)
            #pragma unroll
            for (int q = 0; q < 4; q++) acc[ma][nb][q] = 0.0f;

    #pragma unroll
    for (int kk = 0; kk < 8; kk++) {
        uint32_t k0b = kk * 32;    // 16 elems * 2B
        uint32_t ah[2][4], al[2][4], bh[2][4], bl[2][4];
        #pragma unroll
        for (int ma = 0; ma < 2; ma++) {
            uint32_t off = aRowB + (uint32_t)(ma * 16 * SA * 2) + k0b + aLane;
            ldsm_x4(ah[ma], shb + R_AHI + off);
            ldsm_x4(al[ma], shb + R_ALO + off);
        }
        #pragma unroll
        for (int p = 0; p < 2; p++) {
            uint32_t off = bRowB + (uint32_t)(p * 16 * SA * 2) + k0b + bLane;
            ldsm_x4(bh[p], shb + R_WHI + off);
            ldsm_x4(bl[p], shb + R_WLO + off);
        }
        #pragma unroll
        for (int ma = 0; ma < 2; ma++)
            #pragma unroll
            for (int nb = 0; nb < 4; nb++) {
                int p = nb >> 1, o = (nb & 1) * 2;
                mma16816(acc[ma][nb], ah[ma][0], ah[ma][1], ah[ma][2], ah[ma][3], bh[p][o], bh[p][o + 1]);
                mma16816(acc[ma][nb], ah[ma][0], ah[ma][1], ah[ma][2], ah[ma][3], bl[p][o], bl[p][o + 1]);
                mma16816(acc[ma][nb], al[ma][0], al[ma][1], al[ma][2], al[ma][3], bh[p][o], bh[p][o + 1]);
            }
    }

    if (MODE == 2) __syncthreads();   // tiles dead; about to reuse smem for sF
    float* sF = (float*)sh;           // [64][132]

    #pragma unroll
    for (int ma = 0; ma < 2; ma++)
        #pragma unroll
        for (int nb = 0; nb < 4; nb++) {
            int col = warp_n * 32 + nb * 8 + tig * 2;
            float bs0 = sbias[col], bs1 = sbias[col + 1];
            int r1 = warp_m * 32 + ma * 16 + gid;
            int r2 = r1 + 8;
            float v0 = fmaxf(acc[ma][nb][0] + bs0, 0.0f);
            float v1 = fmaxf(acc[ma][nb][1] + bs1, 0.0f);
            float v2 = fmaxf(acc[ma][nb][2] + bs0, 0.0f);
            float v3 = fmaxf(acc[ma][nb][3] + bs1, 0.0f);
            if (MODE == 0) {
                if (r1 < nr) {
                    __nv_bfloat16 h0 = __float2bfloat16(v0), h1 = __float2bfloat16(v1);
                    __nv_bfloat162 hp; hp.x = h0; hp.y = h1;
                    __nv_bfloat162 lp;
                    lp.x = __float2bfloat16(v0 - __bfloat162float(h0));
                    lp.y = __float2bfloat16(v1 - __bfloat162float(h1));
                    *(uint32_t*)(Ohi + (size_t)(row0 + r1) * 128 + col) = *(uint32_t*)&hp;
                    *(uint32_t*)(Olo + (size_t)(row0 + r1) * 128 + col) = *(uint32_t*)&lp;
                }
                if (r2 < nr) {
                    __nv_bfloat16 h2 = __float2bfloat16(v2), h3 = __float2bfloat16(v3);
                    __nv_bfloat162 hp; hp.x = h2; hp.y = h3;
                    __nv_bfloat162 lp;
                    lp.x = __float2bfloat16(v2 - __bfloat162float(h2));
                    lp.y = __float2bfloat16(v3 - __bfloat162float(h3));
                    *(uint32_t*)(Ohi + (size_t)(row0 + r2) * 128 + col) = *(uint32_t*)&hp;
                    *(uint32_t*)(Olo + (size_t)(row0 + r2) * 128 + col) = *(uint32_t*)&lp;
                }
            } else if (MODE == 1) {
                if (r1 < nr) { float2 p; p.x = v0; p.y = v1;
                    *(float2*)(Of32 + (size_t)(row0 + r1) * 128 + col) = p; }
                if (r2 < nr) { float2 p; p.x = v2; p.y = v3;
                    *(float2*)(Of32 + (size_t)(row0 + r2) * 128 + col) = p; }
            } else {
                float2 p1; p1.x = v0; p1.y = v1;
                float2 p2; p2.x = v2; p2.y = v3;
                *(float2*)(sF + r1 * 132 + col) = p1;
                *(float2*)(sF + r2 * 132 + col) = p2;
            }
        }

    if (MODE == 2) {
        __syncthreads();
        // batch sorted: few segments per tile; 2 threads per column, 32 rows each
        int col = tid & 127, q = tid >> 7;        // q in {0,1}
        int rs = q * 32, re = min(rs + 32, nr);
        float a = 0.0f; int cur = -1;
        for (int r = rs; r < re; r++) {
            int g = sbatch[r];
            if (g != cur) {
                if (cur >= 0) atomicAdd(&g_pool[cur * HIDDEN + col], a);
                cur = g; a = 0.0f;
            }
            a += sF[r * 132 + col];
        }
        if (cur >= 0) atomicAdd(&g_pool[cur * HIDDEN + col], a);
    }
}

// ================= final FC (counts via binary search on sorted batch) =================
__global__ void fc_kernel(const int* __restrict__ batch, const float* __restrict__ Wfc,
                          const float* __restrict__ bfc, float* __restrict__ out) {
    int g = blockIdx.x * blockDim.x + threadIdx.x;
    if (g >= NUM_GRAPHS) return;
    int lo = 0, hi = N_NODES;
    while (lo < hi) { int m = (lo + hi) >> 1; if (batch[m] < g) lo = m + 1; else hi = m; }
    int lb = lo;
    hi = N_NODES;
    while (lo < hi) { int m = (lo + hi) >> 1; if (batch[m] <= g) lo = m + 1; else hi = m; }
    float inv = 1.0f / fmaxf((float)(lo - lb), 1.0f);
    float a0 = 0.0f, a1 = 0.0f;
    const float* row = &g_pool[g * HIDDEN];
    #pragma unroll 4
    for (int k = 0; k < HIDDEN; k++) {
        float v = row[k];
        a0 += v * Wfc[k * 2 + 0];
        a1 += v * Wfc[k * 2 + 1];
    }
    out[g * 2 + 0] = a0 * inv + bfc[0];
    out[g * 2 + 1] = a1 * inv + bfc[1];
}

// ================= launch =================
extern "C" void kernel_launch(void* const* d_in, const int* in_sizes, int n_in,
                              void* d_out, int out_size) {
    const float* x = nullptr;
    const int* ei = nullptr;
    const int* batch = nullptr;
    const float* Ws[4] = {nullptr, nullptr, nullptr, nullptr};
    const float* bs[4] = {nullptr, nullptr, nullptr, nullptr};
    const float* Wfc = nullptr;
    const float* bfc = nullptr;
    int wi = 0, bi = 0;
    for (int i = 0; i < n_in; i++) {
        int sz = in_sizes[i];
        if      (sz == N_NODES * HIDDEN)  x     = (const float*)d_in[i];
        else if (sz == 2 * N_EDGES)       ei    = (const int*)d_in[i];
        else if (sz == N_NODES)           batch = (const int*)d_in[i];
        else if (sz == HIDDEN * HIDDEN)   { if (wi < 4) Ws[wi++] = (const float*)d_in[i]; }
        else if (sz == HIDDEN)            { if (bi < 4) bs[bi++] = (const float*)d_in[i]; }
        else if (sz == HIDDEN * 2)        Wfc   = (const float*)d_in[i];
        else if (sz == 2)                 bfc   = (const float*)d_in[i];
    }
    float* out = (float*)d_out;

    __nv_bfloat16 *Ahi, *Alo, *Mhi, *Mlo, *Whi0, *Wlo0;
    float *H;
    cudaGetSymbolAddress((void**)&Ahi,  g_Ahi);
    cudaGetSymbolAddress((void**)&Alo,  g_Alo);
    cudaGetSymbolAddress((void**)&Mhi,  g_Mhi);
    cudaGetSymbolAddress((void**)&Mlo,  g_Mlo);
    cudaGetSymbolAddress((void**)&H,    g_H);
    cudaGetSymbolAddress((void**)&Whi0, g_Whi);
    cudaGetSymbolAddress((void**)&Wlo0, g_Wlo);

    cudaFuncSetAttribute(gemm_mma<0>, cudaFuncAttributeMaxDynamicSharedMemorySize, GEMM_SMEM);
    cudaFuncSetAttribute(gemm_mma<1>, cudaFuncAttributeMaxDynamicSharedMemorySize, GEMM_SMEM);
    cudaFuncSetAttribute(gemm_mma<2>, cudaFuncAttributeMaxDynamicSharedMemorySize, GEMM_SMEM);

    // CSR build; weight conversion + pool zero ride along with the scan launch
    zero_kernel<<<128, 256>>>();
    hist_kernel<<<(N_EDGES + 255) / 256, 256>>>(ei);
    scan_prep_kernel<<<129, 1024>>>(Ws[0], Ws[1], Ws[2], Ws[3]);
    fill_kernel<<<(N_EDGES + 255) / 256, 256>>>(ei);

    int agg_blocks  = (N_NODES * 32 + 255) / 256;
    int gemm_blocks = (N_NODES + 63) / 64;

    // Layer 1
    agg_conv_kernel<<<agg_blocks, 256>>>((const float4*)x, Ahi, Alo);
    gemm_mma<0><<<gemm_blocks, 256, GEMM_SMEM>>>(Ahi, Alo, Whi0 + 0 * 16384, Wlo0 + 0 * 16384,
                                                 bs[0], Mhi, Mlo, nullptr, nullptr);
    gemm_mma<1><<<gemm_blocks, 256, GEMM_SMEM>>>(Mhi, Mlo, Whi0 + 1 * 16384, Wlo0 + 1 * 16384,
                                                 bs[1], nullptr, nullptr, H, nullptr);
    // Layer 2
    agg_conv_kernel<<<agg_blocks, 256>>>((const float4*)H, Ahi, Alo);
    gemm_mma<0><<<gemm_blocks, 256, GEMM_SMEM>>>(Ahi, Alo, Whi0 + 2 * 16384, Wlo0 + 2 * 16384,
                                                 bs[2], Mhi, Mlo, nullptr, nullptr);
    gemm_mma<2><<<gemm_blocks, 256, GEMM_SMEM>>>(Mhi, Mlo, Whi0 + 3 * 16384, Wlo0 + 3 * 16384,
                                                 bs[3], nullptr, nullptr, nullptr, batch);
    // FC
    fc_kernel<<<(NUM_GRAPHS + 255) / 256, 256>>>(batch, Wfc, bfc, out);
}

// round 16
// speedup vs baseline: 1.5076x; 1.1097x over previous
#include <cuda_runtime.h>
#include <cuda_bf16.h>
#include <cstdint>

#define N_NODES    50000
#define N_EDGES    800000
#define HIDDEN     128
#define NUM_GRAPHS 512

// ================= scratch (static device globals; no allocation) =================
__device__ __nv_bfloat16 g_Ahi[N_NODES * HIDDEN];
__device__ __nv_bfloat16 g_Alo[N_NODES * HIDDEN];
__device__ float         g_H[N_NODES * HIDDEN];
__device__ __nv_bfloat16 g_Whi[4][HIDDEN * HIDDEN];   // transposed: [n][k]
__device__ __nv_bfloat16 g_Wlo[4][HIDDEN * HIDDEN];
__device__ int    g_deg[N_NODES];
__device__ int    g_rowptr[N_NODES + 1];
__device__ int    g_cursor[N_NODES];
__device__ int    g_col[N_EDGES];
__device__ float  g_pool[NUM_GRAPHS * HIDDEN];

// ================= zero degrees (must precede hist) =================
__global__ void zero_kernel() {
    int i = blockIdx.x * blockDim.x + threadIdx.x;
    int st = gridDim.x * blockDim.x;
    for (int j = i; j < N_NODES; j += st) g_deg[j] = 0;
}

// ================= degree histogram (1 edge / thread) =================
__global__ void hist_kernel(const int* __restrict__ ei) {
    int e = blockIdx.x * blockDim.x + threadIdx.x;
    if (e < N_EDGES) {
        int dst = ei[N_EDGES + e];
        if ((unsigned)dst < (unsigned)N_NODES) atomicAdd(&g_deg[dst], 1);
    }
}

// ====== scan (block 0) + weight conversion / pool zero (blocks 1..128) ======
__global__ void scan_prep_kernel(const float* __restrict__ W0, const float* __restrict__ W1,
                                 const float* __restrict__ W2, const float* __restrict__ W3) {
    if (blockIdx.x != 0) {
        int idx = (blockIdx.x - 1) * 1024 + threadIdx.x;   // 0 .. 131071
        if (idx < 4 * HIDDEN * HIDDEN) {
            int q = idx >> 14, j = idx & 16383;
            const float* W = (q == 0) ? W0 : (q == 1) ? W1 : (q == 2) ? W2 : W3;
            int k = j >> 7, n = j & 127;           // W[k][n] row-major
            float v = W[j];
            __nv_bfloat16 h = __float2bfloat16(v);
            g_Whi[q][n * 128 + k] = h;             // B[n][k] = W[k][n]
            g_Wlo[q][n * 128 + k] = __float2bfloat16(v - __bfloat162float(h));
        } else {
            int j = idx - 4 * HIDDEN * HIDDEN;
            if (j < NUM_GRAPHS * HIDDEN) g_pool[j] = 0.0f;
        }
        return;
    }
    __shared__ int warp_sums[32];
    __shared__ int s_carry;
    int tid = threadIdx.x, lane = tid & 31, w = tid >> 5;
    if (tid == 0) { s_carry = 0; g_rowptr[0] = 0; }
    __syncthreads();
    const int N4 = N_NODES / 4;   // 12500
    for (int base = 0; base < N4; base += 1024) {
        int i4 = base + tid;
        int4 v = make_int4(0, 0, 0, 0);
        if (i4 < N4) v = ((const int4*)g_deg)[i4];
        int s0 = v.x, s1 = s0 + v.y, s2 = s1 + v.z, s3 = s2 + v.w;
        int tot = s3;
        int inc = tot;
        #pragma unroll
        for (int o = 1; o < 32; o <<= 1) {
            int t = __shfl_up_sync(0xFFFFFFFFu, inc, o);
            if (lane >= o) inc += t;
        }
        if (lane == 31) warp_sums[w] = inc;
        __syncthreads();
        if (w == 0) {
            int s = warp_sums[lane];
            int si = s;
            #pragma unroll
            for (int o = 1; o < 32; o <<= 1) {
                int t = __shfl_up_sync(0xFFFFFFFFu, si, o);
                if (lane >= o) si += t;
            }
            warp_sums[lane] = si - s;
        }
        __syncthreads();
        int off = s_carry + warp_sums[w] + (inc - tot);
        if (i4 < N4) {
            int b = i4 * 4;
            ((int4*)g_cursor)[i4] = make_int4(off, off + s0, off + s1, off + s2);
            g_rowptr[b + 1] = off + s0;
            g_rowptr[b + 2] = off + s1;
            g_rowptr[b + 3] = off + s2;
            g_rowptr[b + 4] = off + s3;
        }
        __syncthreads();
        int lastT = min(1024, N4 - base) - 1;
        if (tid == lastT) s_carry = off + tot;
        __syncthreads();
    }
}

// ================= CSR fill (1 edge / thread) =================
__global__ void fill_kernel(const int* __restrict__ ei) {
    int e = blockIdx.x * blockDim.x + threadIdx.x;
    if (e < N_EDGES) {
        int src = ei[e];
        int dst = ei[N_EDGES + e];
        if ((unsigned)dst < (unsigned)N_NODES && (unsigned)src < (unsigned)N_NODES) {
            int pos = atomicAdd(&g_cursor[dst], 1);
            g_col[pos] = src;
        }
    }
}

// ================= aggregation + split-bf16 conversion =================
__global__ void agg_conv_kernel(const float4* __restrict__ in,
                                __nv_bfloat16* __restrict__ Ohi,
                                __nv_bfloat16* __restrict__ Olo) {
    int gw = (blockIdx.x * blockDim.x + threadIdx.x) >> 5;
    if (gw >= N_NODES) return;
    int lane = threadIdx.x & 31;
    float4 acc = in[gw * 32 + lane];
    int s = g_rowptr[gw], e = g_rowptr[gw + 1];
    int j = (s < e) ? g_col[s] : 0;
    for (int p = s; p < e; p++) {
        int jn = (p + 1 < e) ? g_col[p + 1] : 0;
        float4 v = in[j * 32 + lane];
        acc.x += v.x; acc.y += v.y; acc.z += v.z; acc.w += v.w;
        j = jn;
    }
    __nv_bfloat16 hx = __float2bfloat16(acc.x), hy = __float2bfloat16(acc.y);
    __nv_bfloat16 hz = __float2bfloat16(acc.z), hw = __float2bfloat16(acc.w);
    __nv_bfloat162 hp0; hp0.x = hx; hp0.y = hy;
    __nv_bfloat162 hp1; hp1.x = hz; hp1.y = hw;
    __nv_bfloat162 lp0; lp0.x = __float2bfloat16(acc.x - __bfloat162float(hx));
                        lp0.y = __float2bfloat16(acc.y - __bfloat162float(hy));
    __nv_bfloat162 lp1; lp1.x = __float2bfloat16(acc.z - __bfloat162float(hz));
                        lp1.y = __float2bfloat16(acc.w - __bfloat162float(hw));
    uint2 hv; hv.x = *(uint32_t*)&hp0; hv.y = *(uint32_t*)&hp1;
    uint2 lv; lv.x = *(uint32_t*)&lp0; lv.y = *(uint32_t*)&lp1;
    *(uint2*)(Ohi + (size_t)gw * 128 + lane * 4) = hv;
    *(uint2*)(Olo + (size_t)gw * 128 + lane * 4) = lv;
}

// ================= persistent fused-layer MLP =================
// relu((relu(A@W1+b1))@W2+b2) per 64-row tile, 148 persistent CTAs, 512 threads.
// W1/W2 hi/lo staged ONCE per CTA; A tiles double-buffered via cp.async;
// intermediate lives in smem (overwrites the consumed A buffer).
// MODE 1: write fp32   MODE 2: fused mean-pool atomics
#define SA 136                        // padded smem row stride (elements); 272B rows
static constexpr int SW1H = 0;        // each W tile: 128*136*2 = 34816 B
static constexpr int SW1L = 34816;
static constexpr int SW2H = 69632;
static constexpr int SW2L = 104448;
static constexpr int SAB  = 139264;   // A buffers: 2 x (hi 17408 + lo 17408)
static constexpr int ABUF = 34816;    // per-buffer size
static constexpr int SB1  = 208896;
static constexpr int SB2  = 209408;
static constexpr int SBT  = 209920;
static constexpr int MLP_SMEM = 210432;
static constexpr int NTILES = (N_NODES + 63) / 64;   // 782
static constexpr int PGRID  = 148;

__device__ __forceinline__ void mma16816(float* c,
    uint32_t a0, uint32_t a1, uint32_t a2, uint32_t a3, uint32_t b0, uint32_t b1) {
    asm volatile(
        "mma.sync.aligned.m16n8k16.row.col.f32.bf16.bf16.f32 "
        "{%0,%1,%2,%3}, {%4,%5,%6,%7}, {%8,%9}, {%0,%1,%2,%3};"
        : "+f"(c[0]), "+f"(c[1]), "+f"(c[2]), "+f"(c[3])
        : "r"(a0), "r"(a1), "r"(a2), "r"(a3), "r"(b0), "r"(b1));
}
__device__ __forceinline__ void ldsm_x4(uint32_t* r, uint32_t addr) {
    asm volatile("ldmatrix.sync.aligned.m8n8.x4.shared.b16 {%0,%1,%2,%3}, [%4];"
        : "=r"(r[0]), "=r"(r[1]), "=r"(r[2]), "=r"(r[3]) : "r"(addr));
}
__device__ __forceinline__ void cpasync16(uint32_t dst, const void* src, int szBytes) {
    asm volatile("cp.async.cg.shared.global [%0], [%1], 16, %2;"
        :: "r"(dst), "l"(src), "r"(szBytes));
}

// 64x128x128 split-GEMM: acc += A(smem,hi/lo) @ W(smem,hi/lo); 16 warps, warp tile 16x32
__device__ __forceinline__ void gemm_pass64(
    uint32_t shb, int aOffH, int aOffL, int wOffH, int wOffL,
    uint32_t aRowB, uint32_t bRowB, uint32_t aLane, uint32_t bLane, float acc[4][4])
{
    #pragma unroll
    for (int kk = 0; kk < 8; kk++) {
        uint32_t k0b = kk * 32;    // 16 elems * 2B
        uint32_t ah[4], al[4], bh[2][4], bl[2][4];
        {
            uint32_t off = aRowB + k0b + aLane;
            ldsm_x4(ah, shb + aOffH + off);
            ldsm_x4(al, shb + aOffL + off);
        }
        #pragma unroll
        for (int p = 0; p < 2; p++) {
            uint32_t off = bRowB + (uint32_t)(p * 16 * SA * 2) + k0b + bLane;
            ldsm_x4(bh[p], shb + wOffH + off);
            ldsm_x4(bl[p], shb + wOffL + off);
        }
        #pragma unroll
        for (int nb = 0; nb < 4; nb++) {
            int p = nb >> 1, o = (nb & 1) * 2;
            mma16816(acc[nb], ah[0], ah[1], ah[2], ah[3], bh[p][o], bh[p][o + 1]);
            mma16816(acc[nb], ah[0], ah[1], ah[2], ah[3], bl[p][o], bl[p][o + 1]);
            mma16816(acc[nb], al[0], al[1], al[2], al[3], bh[p][o], bh[p][o + 1]);
        }
    }
}

template <int MODE>
__global__ void __launch_bounds__(512) mlp_persist(
    const __nv_bfloat16* __restrict__ Ahi, const __nv_bfloat16* __restrict__ Alo,
    const __nv_bfloat16* __restrict__ W1hi, const __nv_bfloat16* __restrict__ W1lo,
    const float* __restrict__ b1,
    const __nv_bfloat16* __restrict__ W2hi, const __nv_bfloat16* __restrict__ W2lo,
    const float* __restrict__ b2,
    float* __restrict__ Of32, const int* __restrict__ batch)
{
    extern __shared__ char sh[];
    float* sb1 = (float*)(sh + SB1);
    float* sb2 = (float*)(sh + SB2);
    int*   sbatch = (int*)(sh + SBT);
    uint32_t shb = (uint32_t)__cvta_generic_to_shared(sh);

    int tid = threadIdx.x;
    if (tid < 128) { sb1[tid] = b1[tid]; sb2[tid] = b2[tid]; }

    // ---- stage W1/W2 hi/lo once (group 0) ----
    #pragma unroll
    for (int it = 0; it < 4; it++) {
        int idx = tid + it * 512;          // 0..2047 per component
        int r = idx >> 4, c = idx & 15;
        uint32_t so = (uint32_t)(r * SA + c * 8) * 2;
        const size_t go = (size_t)r * 128 + c * 8;
        cpasync16(shb + SW1H + so, W1hi + go, 16);
        cpasync16(shb + SW1L + so, W1lo + go, 16);
        cpasync16(shb + SW2H + so, W2hi + go, 16);
        cpasync16(shb + SW2L + so, W2lo + go, 16);
    }
    asm volatile("cp.async.commit_group;");

    // ---- prefetch first A tile into buffer 0 (group 1) ----
    int t0 = blockIdx.x;
    {
        int row0 = t0 * 64, nr = min(64, N_NODES - row0);
        #pragma unroll
        for (int it = 0; it < 2; it++) {
            int idx = tid + it * 512;       // 0..1023
            int r = idx >> 4, c = idx & 15;
            int sz = (r < nr) ? 16 : 0;
            int rs = (r < nr) ? r : 0;
            uint32_t so = (uint32_t)(r * SA + c * 8) * 2;
            cpasync16(shb + SAB + so,         Ahi + (size_t)(row0 + rs) * 128 + c * 8, sz);
            cpasync16(shb + SAB + 17408 + so, Alo + (size_t)(row0 + rs) * 128 + c * 8, sz);
        }
    }
    asm volatile("cp.async.commit_group;");

    int wid = tid >> 5, lid = tid & 31;
    int warp_m = wid >> 2, warp_n = wid & 3;   // 4x4 warp grid; warp tile 16 rows x 32 cols
    int gid = lid >> 2, tig = lid & 3;
    uint32_t aLane = ((lid & 15) * SA + (lid >> 4) * 8) * 2;
    uint32_t bLane = (((lid & 7) + ((lid >> 4) << 3)) * SA + ((lid >> 3) & 1) * 8) * 2;
    uint32_t aRowB = (uint32_t)(warp_m * 16) * SA * 2;
    uint32_t bRowB = (uint32_t)(warp_n * 32) * SA * 2;

    int i = 0;
    for (int t = t0; t < NTILES; t += PGRID, i++) {
        int p = i & 1;
        int aOffH = SAB + p * ABUF, aOffL = aOffH + 17408;
        int row0 = t * 64, nr = min(64, N_NODES - row0);

        // prefetch next tile into the other buffer (its last reader finished
        // before the end-of-iteration barrier of the previous iteration)
        int tn = t + PGRID;
        if (tn < NTILES) {
            int nrow0 = tn * 64, nnr = min(64, N_NODES - nrow0);
            int oOffH = SAB + (1 - p) * ABUF, oOffL = oOffH + 17408;
            #pragma unroll
            for (int it = 0; it < 2; it++) {
                int idx = tid + it * 512;
                int r = idx >> 4, c = idx & 15;
                int sz = (r < nnr) ? 16 : 0;
                int rs = (r < nnr) ? r : 0;
                uint32_t so = (uint32_t)(r * SA + c * 8) * 2;
                cpasync16(shb + oOffH + so, Ahi + (size_t)(nrow0 + rs) * 128 + c * 8, sz);
                cpasync16(shb + oOffL + so, Alo + (size_t)(nrow0 + rs) * 128 + c * 8, sz);
            }
        }
        asm volatile("cp.async.commit_group;");

        if (MODE == 2 && tid < 64)
            sbatch[tid] = (tid < nr) ? batch[row0 + tid] : -1;

        asm volatile("cp.async.wait_group 1;");   // current buffer (and W) ready
        __syncthreads();

        float acc[4][4];
        #pragma unroll
        for (int nb = 0; nb < 4; nb++)
            #pragma unroll
            for (int q = 0; q < 4; q++) acc[nb][q] = 0.0f;

        // ---- GEMM1: A @ W1 ----
        gemm_pass64(shb, aOffH, aOffL, SW1H, SW1L, aRowB, bRowB, aLane, bLane, acc);
        __syncthreads();   // A-tile reads done; safe to overwrite with intermediate

        // ---- intermediate: bias1 + relu + hi/lo split into the consumed A buffer ----
        __nv_bfloat16* iAhi = (__nv_bfloat16*)(sh + aOffH);
        __nv_bfloat16* iAlo = (__nv_bfloat16*)(sh + aOffL);
        #pragma unroll
        for (int nb = 0; nb < 4; nb++) {
            int col = warp_n * 32 + nb * 8 + tig * 2;
            float bs0 = sb1[col], bs1v = sb1[col + 1];
            int r1 = warp_m * 16 + gid, r2 = r1 + 8;
            float v0 = fmaxf(acc[nb][0] + bs0, 0.0f);
            float v1 = fmaxf(acc[nb][1] + bs1v, 0.0f);
            float v2 = fmaxf(acc[nb][2] + bs0, 0.0f);
            float v3 = fmaxf(acc[nb][3] + bs1v, 0.0f);
            __nv_bfloat16 h0 = __float2bfloat16(v0), h1 = __float2bfloat16(v1);
            __nv_bfloat16 h2 = __float2bfloat16(v2), h3 = __float2bfloat16(v3);
            __nv_bfloat162 hpA; hpA.x = h0; hpA.y = h1;
            __nv_bfloat162 hpB; hpB.x = h2; hpB.y = h3;
            __nv_bfloat162 lpA;
            lpA.x = __float2bfloat16(v0 - __bfloat162float(h0));
            lpA.y = __float2bfloat16(v1 - __bfloat162float(h1));
            __nv_bfloat162 lpB;
            lpB.x = __float2bfloat16(v2 - __bfloat162float(h2));
            lpB.y = __float2bfloat16(v3 - __bfloat162float(h3));
            *(uint32_t*)(iAhi + r1 * SA + col) = *(uint32_t*)&hpA;
            *(uint32_t*)(iAhi + r2 * SA + col) = *(uint32_t*)&hpB;
            *(uint32_t*)(iAlo + r1 * SA + col) = *(uint32_t*)&lpA;
            *(uint32_t*)(iAlo + r2 * SA + col) = *(uint32_t*)&lpB;
            acc[nb][0] = 0.0f; acc[nb][1] = 0.0f; acc[nb][2] = 0.0f; acc[nb][3] = 0.0f;
        }
        __syncthreads();

        // ---- GEMM2: intermediate @ W2 ----
        gemm_pass64(shb, aOffH, aOffL, SW2H, SW2L, aRowB, bRowB, aLane, bLane, acc);

        // ---- epilogue ----
        if (MODE == 1) {
            #pragma unroll
            for (int nb = 0; nb < 4; nb++) {
                int col = warp_n * 32 + nb * 8 + tig * 2;
                float bs0 = sb2[col], bs1v = sb2[col + 1];
                int r1 = warp_m * 16 + gid, r2 = r1 + 8;
                if (r1 < nr) { float2 pr; pr.x = fmaxf(acc[nb][0] + bs0, 0.0f);
                    pr.y = fmaxf(acc[nb][1] + bs1v, 0.0f);
                    *(float2*)(Of32 + (size_t)(row0 + r1) * 128 + col) = pr; }
                if (r2 < nr) { float2 pr; pr.x = fmaxf(acc[nb][2] + bs0, 0.0f);
                    pr.y = fmaxf(acc[nb][3] + bs1v, 0.0f);
                    *(float2*)(Of32 + (size_t)(row0 + r2) * 128 + col) = pr; }
            }
        } else {
            __syncthreads();   // intermediate reads done; reuse buffer as sF
            float* sF = (float*)(sh + aOffH);    // [64][132] = 33792 B <= 34816
            #pragma unroll
            for (int nb = 0; nb < 4; nb++) {
                int col = warp_n * 32 + nb * 8 + tig * 2;
                float bs0 = sb2[col], bs1v = sb2[col + 1];
                int r1 = warp_m * 16 + gid, r2 = r1 + 8;
                float2 p1; p1.x = fmaxf(acc[nb][0] + bs0, 0.0f);
                           p1.y = fmaxf(acc[nb][1] + bs1v, 0.0f);
                float2 p2; p2.x = fmaxf(acc[nb][2] + bs0, 0.0f);
                           p2.y = fmaxf(acc[nb][3] + bs1v, 0.0f);
                *(float2*)(sF + r1 * 132 + col) = p1;
                *(float2*)(sF + r2 * 132 + col) = p2;
            }
            __syncthreads();
            // batch sorted: few segments per tile; 4 threads/col, 16 rows each
            int col = tid & 127, q = tid >> 7;
            int rs = q * 16, re = min(rs + 16, nr);
            float a = 0.0f; int cur = -1;
            for (int r = rs; r < re; r++) {
                int g = sbatch[r];
                if (g != cur) {
                    if (cur >= 0) atomicAdd(&g_pool[cur * HIDDEN + col], a);
                    cur = g; a = 0.0f;
                }
                a += sF[r * 132 + col];
            }
            if (cur >= 0) atomicAdd(&g_pool[cur * HIDDEN + col], a);
        }
        __syncthreads();   // everyone done with buf[p] before next iter prefetches into buf[1-p]... and re-reads sbatch
    }
}

// ================= final FC (counts via binary search on sorted batch) =================
__global__ void fc_kernel(const int* __restrict__ batch, const float* __restrict__ Wfc,
                          const float* __restrict__ bfc, float* __restrict__ out) {
    int g = blockIdx.x * blockDim.x + threadIdx.x;
    if (g >= NUM_GRAPHS) return;
    int lo = 0, hi = N_NODES;
    while (lo < hi) { int m = (lo + hi) >> 1; if (batch[m] < g) lo = m + 1; else hi = m; }
    int lb = lo;
    hi = N_NODES;
    while (lo < hi) { int m = (lo + hi) >> 1; if (batch[m] <= g) lo = m + 1; else hi = m; }
    float inv = 1.0f / fmaxf((float)(lo - lb), 1.0f);
    float a0 = 0.0f, a1 = 0.0f;
    const float* row = &g_pool[g * HIDDEN];
    #pragma unroll 4
    for (int k = 0; k < HIDDEN; k++) {
        float v = row[k];
        a0 += v * Wfc[k * 2 + 0];
        a1 += v * Wfc[k * 2 + 1];
    }
    out[g * 2 + 0] = a0 * inv + bfc[0];
    out[g * 2 + 1] = a1 * inv + bfc[1];
}

// ================= launch =================
extern "C" void kernel_launch(void* const* d_in, const int* in_sizes, int n_in,
                              void* d_out, int out_size) {
    const float* x = nullptr;
    const int* ei = nullptr;
    const int* batch = nullptr;
    const float* Ws[4] = {nullptr, nullptr, nullptr, nullptr};
    const float* bs[4] = {nullptr, nullptr, nullptr, nullptr};
    const float* Wfc = nullptr;
    const float* bfc = nullptr;
    int wi = 0, bi = 0;
    for (int i = 0; i < n_in; i++) {
        int sz = in_sizes[i];
        if      (sz == N_NODES * HIDDEN)  x     = (const float*)d_in[i];
        else if (sz == 2 * N_EDGES)       ei    = (const int*)d_in[i];
        else if (sz == N_NODES)           batch = (const int*)d_in[i];
        else if (sz == HIDDEN * HIDDEN)   { if (wi < 4) Ws[wi++] = (const float*)d_in[i]; }
        else if (sz == HIDDEN)            { if (bi < 4) bs[bi++] = (const float*)d_in[i]; }
        else if (sz == HIDDEN * 2)        Wfc   = (const float*)d_in[i];
        else if (sz == 2)                 bfc   = (const float*)d_in[i];
    }
    float* out = (float*)d_out;

    __nv_bfloat16 *Ahi, *Alo, *Whi0, *Wlo0;
    float *H;
    cudaGetSymbolAddress((void**)&Ahi,  g_Ahi);
    cudaGetSymbolAddress((void**)&Alo,  g_Alo);
    cudaGetSymbolAddress((void**)&H,    g_H);
    cudaGetSymbolAddress((void**)&Whi0, g_Whi);
    cudaGetSymbolAddress((void**)&Wlo0, g_Wlo);

    cudaFuncSetAttribute(mlp_persist<1>, cudaFuncAttributeMaxDynamicSharedMemorySize, MLP_SMEM);
    cudaFuncSetAttribute(mlp_persist<2>, cudaFuncAttributeMaxDynamicSharedMemorySize, MLP_SMEM);

    // CSR build; weight conversion + pool zero ride along with the scan launch
    zero_kernel<<<128, 256>>>();
    hist_kernel<<<(N_EDGES + 255) / 256, 256>>>(ei);
    scan_prep_kernel<<<129, 1024>>>(Ws[0], Ws[1], Ws[2], Ws[3]);
    fill_kernel<<<(N_EDGES + 255) / 256, 256>>>(ei);

    int agg_blocks = (N_NODES * 32 + 255) / 256;

    // Layer 1 (agg -> persistent fused MLP -> fp32 H)
    agg_conv_kernel<<<agg_blocks, 256>>>((const float4*)x, Ahi, Alo);
    mlp_persist<1><<<PGRID, 512, MLP_SMEM>>>(Ahi, Alo,
        Whi0 + 0 * 16384, Wlo0 + 0 * 16384, bs[0],
        Whi0 + 1 * 16384, Wlo0 + 1 * 16384, bs[1], H, nullptr);

    // Layer 2 (agg -> persistent fused MLP -> fused mean-pool)
    agg_conv_kernel<<<agg_blocks, 256>>>((const float4*)H, Ahi, Alo);
    mlp_persist<2><<<PGRID, 512, MLP_SMEM>>>(Ahi, Alo,
        Whi0 + 2 * 16384, Wlo0 + 2 * 16384, bs[2],
        Whi0 + 3 * 16384, Wlo0 + 3 * 16384, bs[3], nullptr, batch);

    // FC
    fc_kernel<<<(NUM_GRAPHS + 255) / 256, 256>>>(batch, Wfc, bfc, out);
}